// round 13
// baseline (speedup 1.0000x reference)
#include <cuda_runtime.h>

// Pure HBM-streaming quadratic form:
//   total = sum over pairs (l1<=l2), weight w in {1,2}:
//           w * sum_s d1[s,:] . O[s,:,:] . d2[s,:],   d = c_in - c_tgt
// Overlap tensors: 356.5 MB read once -> memory-bound (6.68 TB/s achieved).
// R13 = R12 (256-bit loads + PDL) with:
//   - explicit griddepcontrol.launch_dependents early trigger in prep
//     (release rho at last prep thread, skip grid-retire latency)
//   - vectorized 32-block prep (shorter primary kernel).

#define TPB 256
#define IT  2                 // float8 (32B) per thread per iter; unit = 256*2*8 = 4096 floats
#define NUNITS 21760

// delta coefficients, concatenated by l:
//   l0: [0,2048), l1: [2048,8192), l2: [8192,18432), l3: [18432,32768)
__device__ __align__(32) float g_d[32768];

// Vectorized prep: 32 blocks x 256 threads, 4 float4 per thread (32768 floats).
// Each thread: compute d for its 4 float4 slots, fence, early-trigger PDL.
__global__ void prep_kernel(const float4* __restrict__ i0, const float4* __restrict__ t0,
                            const float4* __restrict__ i1, const float4* __restrict__ t1,
                            const float4* __restrict__ i2, const float4* __restrict__ t2,
                            const float4* __restrict__ i3, const float4* __restrict__ t3,
                            float* out) {
    int tid4 = blockIdx.x * blockDim.x + threadIdx.x;   // float4 index base
    if (tid4 == 0) out[0] = 0.0f;
    float4* gd4 = (float4*)g_d;
#pragma unroll
    for (int k = 0; k < 4; ++k) {
        int idx = tid4 + k * 8192;          // float4 index into g_d [0, 8192) per k
        // boundaries in float4 units: l0 [0,512), l1 [512,2048), l2 [2048,4608), l3 [4608,8192)
        float4 a, b;
        if (idx < 512)        { a = i0[idx];        b = t0[idx]; }
        else if (idx < 2048)  { a = i1[idx - 512];  b = t1[idx - 512]; }
        else if (idx < 4608)  { a = i2[idx - 2048]; b = t2[idx - 2048]; }
        else                  { a = i3[idx - 4608]; b = t3[idx - 4608]; }
        gd4[idx] = make_float4(a.x - b.x, a.y - b.y, a.z - b.z, a.w - b.w);
    }
    __threadfence();
    // Early PDL trigger: dependent grid may launch once ALL threads pass this.
    asm volatile("griddepcontrol.launch_dependents;" ::: "memory");
}

struct OvlpPtrs { const float* p[10]; };

// 256-bit streamed load (evict-first) — sm_103a LDG.E.256
__device__ __forceinline__ void ldg256_cs(const float* p, float v[8]) {
    asm volatile("ld.global.cs.v8.f32 {%0,%1,%2,%3,%4,%5,%6,%7}, [%8];"
                 : "=f"(v[0]), "=f"(v[1]), "=f"(v[2]), "=f"(v[3]),
                   "=f"(v[4]), "=f"(v[5]), "=f"(v[6]), "=f"(v[7])
                 : "l"(p));
}
// 256-bit read-only cached load (L1-resident d2)
__device__ __forceinline__ void ldg256_nc(const float* p, float v[8]) {
    asm volatile("ld.global.nc.v8.f32 {%0,%1,%2,%3,%4,%5,%6,%7}, [%8];"
                 : "=f"(v[0]), "=f"(v[1]), "=f"(v[2]), "=f"(v[3]),
                   "=f"(v[4]), "=f"(v[5]), "=f"(v[6]), "=f"(v[7])
                 : "l"(p));
}

// One unit of one pair; linear float order, 32B granules.
template <int D1, int D2, int W, int OFF1, int OFF2>
__device__ __forceinline__ float unit_acc(const float* __restrict__ o, int lu, int tid) {
    constexpr unsigned C8 = D2 / 8;   // float8 columns per row; multiple of 32
    float acc = 0.0f;
    unsigned base = (unsigned)lu * (TPB * IT) + tid;   // in float8 units
#pragma unroll
    for (int it = 0; it < IT; ++it) {
        unsigned idx8 = base + (unsigned)it * TPB;
        unsigned c8 = idx8 % C8;                  // compile-time divisor -> mul-shift
        unsigned rs = idx8 / C8;
        unsigned r  = rs % (unsigned)D1;
        unsigned s  = rs / (unsigned)D1;
        float ov[8], d2[8];
        ldg256_cs(o + idx8 * 8, ov);                       // streamed, evict-first
        ldg256_nc(g_d + OFF2 + s * D2 + c8 * 8, d2);       // L1-resident
        float d1 = __ldg(&g_d[OFF1 + s * D1 + r]);         // warp-uniform broadcast
        float dot = ov[0] * d2[0];
        dot = fmaf(ov[1], d2[1], dot);
        dot = fmaf(ov[2], d2[2], dot);
        dot = fmaf(ov[3], d2[3], dot);
        dot = fmaf(ov[4], d2[4], dot);
        dot = fmaf(ov[5], d2[5], dot);
        dot = fmaf(ov[6], d2[6], dot);
        dot = fmaf(ov[7], d2[7], dot);
        acc = fmaf(d1, dot, acc);
    }
    return (W == 2) ? (acc + acc) : acc;   // weight once per block
}

// Unit-count prefix sums (unit = 4096 floats):
// (0,0):128 (0,1):512 (0,2):1152 (0,3):2048 (1,1):3200
// (1,2):5120 (1,3):7808 (2,2):11008 (2,3):15488 (3,3):21760
__global__ void __launch_bounds__(TPB, 8) rho_kernel(OvlpPtrs o, float* __restrict__ out) {
    // PDL: wait for prep's early trigger (g_d/out writes visible after this).
    asm volatile("griddepcontrol.wait;" ::: "memory");

    int b = blockIdx.x;
    int tid = threadIdx.x;
    float acc;
    if      (b <   128) acc = unit_acc< 256,  256, 1,     0,     0>(o.p[0], b,         tid);
    else if (b <   512) acc = unit_acc< 256,  768, 2,     0,  2048>(o.p[1], b -   128, tid);
    else if (b <  1152) acc = unit_acc< 256, 1280, 2,     0,  8192>(o.p[2], b -   512, tid);
    else if (b <  2048) acc = unit_acc< 256, 1792, 2,     0, 18432>(o.p[3], b -  1152, tid);
    else if (b <  3200) acc = unit_acc< 768,  768, 1,  2048,  2048>(o.p[4], b -  2048, tid);
    else if (b <  5120) acc = unit_acc< 768, 1280, 2,  2048,  8192>(o.p[5], b -  3200, tid);
    else if (b <  7808) acc = unit_acc< 768, 1792, 2,  2048, 18432>(o.p[6], b -  5120, tid);
    else if (b < 11008) acc = unit_acc<1280, 1280, 1,  8192,  8192>(o.p[7], b -  7808, tid);
    else if (b < 15488) acc = unit_acc<1280, 1792, 2,  8192, 18432>(o.p[8], b - 11008, tid);
    else                acc = unit_acc<1792, 1792, 1, 18432, 18432>(o.p[9], b - 15488, tid);

    // warp reduce
#pragma unroll
    for (int off = 16; off > 0; off >>= 1)
        acc += __shfl_down_sync(0xffffffffu, acc, off);

    __shared__ float ws[TPB / 32];
    if ((tid & 31) == 0) ws[tid >> 5] = acc;
    __syncthreads();
    if (tid == 0) {
        float s = ws[0];
#pragma unroll
        for (int w = 1; w < TPB / 32; ++w) s += ws[w];
        atomicAdd(out, s);
    }
}

extern "C" void kernel_launch(void* const* d_in, const int* in_sizes, int n_in,
                              void* d_out, int out_size) {
    (void)in_sizes; (void)n_in; (void)out_size;
    OvlpPtrs o;
    for (int k = 0; k < 10; ++k) o.p[k] = (const float*)d_in[8 + k];
    float* out = (float*)d_out;

    prep_kernel<<<32, TPB>>>((const float4*)d_in[0], (const float4*)d_in[1],
                             (const float4*)d_in[2], (const float4*)d_in[3],
                             (const float4*)d_in[4], (const float4*)d_in[5],
                             (const float4*)d_in[6], (const float4*)d_in[7], out);

    // PDL launch: rho begins launching while prep executes; griddepcontrol.wait
    // inside rho enforces the dependency with memory visibility.
    cudaLaunchConfig_t cfg = {};
    cfg.gridDim = dim3(NUNITS);
    cfg.blockDim = dim3(TPB);
    cfg.dynamicSmemBytes = 0;
    cfg.stream = 0;
    cudaLaunchAttribute attrs[1];
    attrs[0].id = cudaLaunchAttributeProgrammaticStreamSerialization;
    attrs[0].val.programmaticStreamSerializationAllowed = 1;
    cfg.attrs = attrs;
    cfg.numAttrs = 1;
    cudaLaunchKernelEx(&cfg, rho_kernel, o, out);
}

// round 14
// speedup vs baseline: 1.1067x; 1.1067x over previous
#include <cuda_runtime.h>

// Pure HBM-streaming quadratic form:
//   total = sum over pairs (l1<=l2), weight w in {1,2}:
//           w * sum_s d1[s,:] . O[s,:,:] . d2[s,:],   d = c_in - c_tgt
// Overlap tensors: 356.5 MB read once -> memory-bound (6.68 TB/s achieved).
// R14 = R12 exactly (256-bit loads; PDL with IMPLICIT sync only — the R13
//       early trigger caused a synchronized first-wave LDG burst and is
//       removed) + slim 32-block float4 prep.

#define TPB 256
#define IT  2                 // float8 (32B) per thread per iter; unit = 256*2*8 = 4096 floats
#define NUNITS 21760

// delta coefficients, concatenated by l:
//   l0: [0,2048), l1: [2048,8192), l2: [8192,18432), l3: [18432,32768)
__device__ __align__(32) float g_d[32768];

// Vectorized prep: 32 blocks x 256 threads, 4 float4 per thread (32768 floats).
__global__ void prep_kernel(const float4* __restrict__ i0, const float4* __restrict__ t0,
                            const float4* __restrict__ i1, const float4* __restrict__ t1,
                            const float4* __restrict__ i2, const float4* __restrict__ t2,
                            const float4* __restrict__ i3, const float4* __restrict__ t3,
                            float* out) {
    int tid4 = blockIdx.x * blockDim.x + threadIdx.x;   // float4 index base
    if (tid4 == 0) out[0] = 0.0f;
    float4* gd4 = (float4*)g_d;
#pragma unroll
    for (int k = 0; k < 4; ++k) {
        int idx = tid4 + k * 8192;          // float4 index into g_d, [0, 8192) per k
        // float4-unit boundaries: l0 [0,512), l1 [512,2048), l2 [2048,4608), l3 [4608,8192)
        float4 a, b;
        if (idx < 512)        { a = i0[idx];        b = t0[idx]; }
        else if (idx < 2048)  { a = i1[idx - 512];  b = t1[idx - 512]; }
        else if (idx < 4608)  { a = i2[idx - 2048]; b = t2[idx - 2048]; }
        else                  { a = i3[idx - 4608]; b = t3[idx - 4608]; }
        gd4[idx] = make_float4(a.x - b.x, a.y - b.y, a.z - b.z, a.w - b.w);
    }
    // No early trigger: dependent launches at grid completion (implicit PDL),
    // which both staggers rho's wave start and guarantees g_d visibility.
}

struct OvlpPtrs { const float* p[10]; };

// 256-bit streamed load (evict-first) — sm_103a LDG.E.256
__device__ __forceinline__ void ldg256_cs(const float* p, float v[8]) {
    asm volatile("ld.global.cs.v8.f32 {%0,%1,%2,%3,%4,%5,%6,%7}, [%8];"
                 : "=f"(v[0]), "=f"(v[1]), "=f"(v[2]), "=f"(v[3]),
                   "=f"(v[4]), "=f"(v[5]), "=f"(v[6]), "=f"(v[7])
                 : "l"(p));
}
// 256-bit read-only cached load (L1-resident d2)
__device__ __forceinline__ void ldg256_nc(const float* p, float v[8]) {
    asm volatile("ld.global.nc.v8.f32 {%0,%1,%2,%3,%4,%5,%6,%7}, [%8];"
                 : "=f"(v[0]), "=f"(v[1]), "=f"(v[2]), "=f"(v[3]),
                   "=f"(v[4]), "=f"(v[5]), "=f"(v[6]), "=f"(v[7])
                 : "l"(p));
}

// One unit of one pair; linear float order, 32B granules.
template <int D1, int D2, int W, int OFF1, int OFF2>
__device__ __forceinline__ float unit_acc(const float* __restrict__ o, int lu, int tid) {
    constexpr unsigned C8 = D2 / 8;   // float8 columns per row; multiple of 32
    float acc = 0.0f;
    unsigned base = (unsigned)lu * (TPB * IT) + tid;   // in float8 units
#pragma unroll
    for (int it = 0; it < IT; ++it) {
        unsigned idx8 = base + (unsigned)it * TPB;
        unsigned c8 = idx8 % C8;                  // compile-time divisor -> mul-shift
        unsigned rs = idx8 / C8;
        unsigned r  = rs % (unsigned)D1;
        unsigned s  = rs / (unsigned)D1;
        float ov[8], d2[8];
        ldg256_cs(o + idx8 * 8, ov);                       // streamed, evict-first
        ldg256_nc(g_d + OFF2 + s * D2 + c8 * 8, d2);       // L1-resident
        float d1 = __ldg(&g_d[OFF1 + s * D1 + r]);         // warp-uniform broadcast
        float dot = ov[0] * d2[0];
        dot = fmaf(ov[1], d2[1], dot);
        dot = fmaf(ov[2], d2[2], dot);
        dot = fmaf(ov[3], d2[3], dot);
        dot = fmaf(ov[4], d2[4], dot);
        dot = fmaf(ov[5], d2[5], dot);
        dot = fmaf(ov[6], d2[6], dot);
        dot = fmaf(ov[7], d2[7], dot);
        acc = fmaf(d1, dot, acc);
    }
    return (W == 2) ? (acc + acc) : acc;   // weight once per block
}

// Unit-count prefix sums (unit = 4096 floats):
// (0,0):128 (0,1):512 (0,2):1152 (0,3):2048 (1,1):3200
// (1,2):5120 (1,3):7808 (2,2):11008 (2,3):15488 (3,3):21760
__global__ void __launch_bounds__(TPB, 8) rho_kernel(OvlpPtrs o, float* __restrict__ out) {
    // PDL: wait for prep grid (implicit trigger at its completion).
    asm volatile("griddepcontrol.wait;" ::: "memory");

    int b = blockIdx.x;
    int tid = threadIdx.x;
    float acc;
    if      (b <   128) acc = unit_acc< 256,  256, 1,     0,     0>(o.p[0], b,         tid);
    else if (b <   512) acc = unit_acc< 256,  768, 2,     0,  2048>(o.p[1], b -   128, tid);
    else if (b <  1152) acc = unit_acc< 256, 1280, 2,     0,  8192>(o.p[2], b -   512, tid);
    else if (b <  2048) acc = unit_acc< 256, 1792, 2,     0, 18432>(o.p[3], b -  1152, tid);
    else if (b <  3200) acc = unit_acc< 768,  768, 1,  2048,  2048>(o.p[4], b -  2048, tid);
    else if (b <  5120) acc = unit_acc< 768, 1280, 2,  2048,  8192>(o.p[5], b -  3200, tid);
    else if (b <  7808) acc = unit_acc< 768, 1792, 2,  2048, 18432>(o.p[6], b -  5120, tid);
    else if (b < 11008) acc = unit_acc<1280, 1280, 1,  8192,  8192>(o.p[7], b -  7808, tid);
    else if (b < 15488) acc = unit_acc<1280, 1792, 2,  8192, 18432>(o.p[8], b - 11008, tid);
    else                acc = unit_acc<1792, 1792, 1, 18432, 18432>(o.p[9], b - 15488, tid);

    // warp reduce
#pragma unroll
    for (int off = 16; off > 0; off >>= 1)
        acc += __shfl_down_sync(0xffffffffu, acc, off);

    __shared__ float ws[TPB / 32];
    if ((tid & 31) == 0) ws[tid >> 5] = acc;
    __syncthreads();
    if (tid == 0) {
        float s = ws[0];
#pragma unroll
        for (int w = 1; w < TPB / 32; ++w) s += ws[w];
        atomicAdd(out, s);
    }
}

extern "C" void kernel_launch(void* const* d_in, const int* in_sizes, int n_in,
                              void* d_out, int out_size) {
    (void)in_sizes; (void)n_in; (void)out_size;
    OvlpPtrs o;
    for (int k = 0; k < 10; ++k) o.p[k] = (const float*)d_in[8 + k];
    float* out = (float*)d_out;

    prep_kernel<<<32, TPB>>>((const float4*)d_in[0], (const float4*)d_in[1],
                             (const float4*)d_in[2], (const float4*)d_in[3],
                             (const float4*)d_in[4], (const float4*)d_in[5],
                             (const float4*)d_in[6], (const float4*)d_in[7], out);

    // PDL launch with IMPLICIT sync: rho's launch ramp overlaps prep's
    // execution; blocks release at prep grid completion (staggered start).
    cudaLaunchConfig_t cfg = {};
    cfg.gridDim = dim3(NUNITS);
    cfg.blockDim = dim3(TPB);
    cfg.dynamicSmemBytes = 0;
    cfg.stream = 0;
    cudaLaunchAttribute attrs[1];
    attrs[0].id = cudaLaunchAttributeProgrammaticStreamSerialization;
    attrs[0].val.programmaticStreamSerializationAllowed = 1;
    cfg.attrs = attrs;
    cfg.numAttrs = 1;
    cudaLaunchKernelEx(&cfg, rho_kernel, o, out);
}